// round 5
// baseline (speedup 1.0000x reference)
#include <cuda_runtime.h>
#include <math.h>

#define N_EMBD 1024
#define SEQ    2048
#define BATCH  2
#define NHEAD  16
#define DHEAD  64
#define FFDIM  4096
#define MROWS  (BATCH*SEQ)   // 4096
#define LOG2E  1.4426950408889634f

// ---------------- scratch (allocation-free: __device__ globals) ----------------
__device__ float g_h   [(size_t)MROWS * N_EMBD];
__device__ float g_q   [(size_t)MROWS * N_EMBD];
__device__ float g_k   [(size_t)MROWS * N_EMBD];
__device__ float g_v   [(size_t)MROWS * N_EMBD];
__device__ float g_attn[(size_t)MROWS * N_EMBD];
__device__ float g_ff  [(size_t)MROWS * FFDIM];

// ---------------- LayerNorm: one block per row ----------------
__global__ void __launch_bounds__(256) ln_kernel(
    const float* __restrict__ x, const float* __restrict__ w,
    const float* __restrict__ b, float* __restrict__ out)
{
    int row = blockIdx.x;
    int tid = threadIdx.x;
    const float* xr = x + (size_t)row * N_EMBD;

    float4 xv = *(const float4*)(xr + tid * 4);
    float s  = xv.x + xv.y + xv.z + xv.w;
    float ss = xv.x*xv.x + xv.y*xv.y + xv.z*xv.z + xv.w*xv.w;

    #pragma unroll
    for (int o = 16; o; o >>= 1) {
        s  += __shfl_xor_sync(0xffffffffu, s,  o);
        ss += __shfl_xor_sync(0xffffffffu, ss, o);
    }
    __shared__ float sb[8], ssb[8];
    int wid = tid >> 5, lane = tid & 31;
    if (lane == 0) { sb[wid] = s; ssb[wid] = ss; }
    __syncthreads();
    if (wid == 0) {
        s  = (lane < 8) ? sb[lane]  : 0.f;
        ss = (lane < 8) ? ssb[lane] : 0.f;
        #pragma unroll
        for (int o = 4; o; o >>= 1) {
            s  += __shfl_xor_sync(0xffffffffu, s,  o);
            ss += __shfl_xor_sync(0xffffffffu, ss, o);
        }
        if (lane == 0) { sb[0] = s; ssb[0] = ss; }
    }
    __syncthreads();
    s = sb[0]; ss = ssb[0];

    float mu   = s * (1.0f / N_EMBD);
    float var  = ss * (1.0f / N_EMBD) - mu * mu;
    float rstd = rsqrtf(var + 1e-5f);

    float4 wv = *(const float4*)(w + tid * 4);
    float4 bv = *(const float4*)(b + tid * 4);
    float4 ov;
    ov.x = (xv.x - mu) * rstd * wv.x + bv.x;
    ov.y = (xv.y - mu) * rstd * wv.y + bv.y;
    ov.z = (xv.z - mu) * rstd * wv.z + bv.z;
    ov.w = (xv.w - mu) * rstd * wv.w + bv.w;
    *(float4*)(out + (size_t)row * N_EMBD + tid * 4) = ov;
}

// ---------------- SGEMM: C = epilogue(A[M,K] @ B[K,N]) ----------------
// BM=BN=128, BK=16, 256 threads, 8x8 accum per thread. All dims are multiples
// of the tile sizes for this problem, so no bounds checks.
template<int RELU, int HASB, int HASR>
__global__ void __launch_bounds__(256) sgemm(
    const float* __restrict__ A, const float* __restrict__ B,
    const float* __restrict__ bias, const float* __restrict__ res,
    float* __restrict__ C, int M, int N, int K)
{
    const int BK = 16;
    __shared__ float As[16 * 132];   // transposed: As[k][m], padded stride 132
    __shared__ float Bs[16 * 132];   // Bs[k][n],  padded stride 132

    int tid = threadIdx.x;
    int tx = tid & 15, ty = tid >> 4;
    int m0 = blockIdx.y * 128, n0 = blockIdx.x * 128;

    float acc[8][8];
    #pragma unroll
    for (int i = 0; i < 8; i++)
        #pragma unroll
        for (int j = 0; j < 8; j++) acc[i][j] = 0.f;

    int nt = K / BK;
    for (int t = 0; t < nt; t++) {
        int k0 = t * BK;
        // A tile: 128 rows x 16 cols = 512 float4
        #pragma unroll
        for (int i = 0; i < 2; i++) {
            int f = tid + i * 256;
            int r = f >> 2, c4 = f & 3;
            float4 a = *(const float4*)&A[(size_t)(m0 + r) * K + k0 + c4 * 4];
            As[(c4 * 4 + 0) * 132 + r] = a.x;
            As[(c4 * 4 + 1) * 132 + r] = a.y;
            As[(c4 * 4 + 2) * 132 + r] = a.z;
            As[(c4 * 4 + 3) * 132 + r] = a.w;
        }
        // B tile: 16 rows x 128 cols = 512 float4
        #pragma unroll
        for (int i = 0; i < 2; i++) {
            int f = tid + i * 256;
            int r = f >> 5, c4 = f & 31;
            *(float4*)&Bs[r * 132 + c4 * 4] =
                *(const float4*)&B[(size_t)(k0 + r) * N + n0 + c4 * 4];
        }
        __syncthreads();

        #pragma unroll
        for (int kk = 0; kk < BK; kk++) {
            float ra[8], rb[8];
            *(float4*)&ra[0] = *(const float4*)&As[kk * 132 + ty * 8];
            *(float4*)&ra[4] = *(const float4*)&As[kk * 132 + ty * 8 + 4];
            *(float4*)&rb[0] = *(const float4*)&Bs[kk * 132 + tx * 8];
            *(float4*)&rb[4] = *(const float4*)&Bs[kk * 132 + tx * 8 + 4];
            #pragma unroll
            for (int i = 0; i < 8; i++)
                #pragma unroll
                for (int j = 0; j < 8; j++)
                    acc[i][j] = fmaf(ra[i], rb[j], acc[i][j]);
        }
        __syncthreads();
    }

    // epilogue: (+bias) -> (relu) -> (+residual)
    #pragma unroll
    for (int i = 0; i < 8; i++) {
        size_t row = (size_t)(m0 + ty * 8 + i);
        size_t off = row * N + n0 + tx * 8;
        #pragma unroll
        for (int jj = 0; jj < 2; jj++) {
            float4 o;
            o.x = acc[i][jj * 4 + 0];
            o.y = acc[i][jj * 4 + 1];
            o.z = acc[i][jj * 4 + 2];
            o.w = acc[i][jj * 4 + 3];
            if (HASB) {
                float4 bb = *(const float4*)&bias[n0 + tx * 8 + jj * 4];
                o.x += bb.x; o.y += bb.y; o.z += bb.z; o.w += bb.w;
            }
            if (RELU) {
                o.x = fmaxf(o.x, 0.f); o.y = fmaxf(o.y, 0.f);
                o.z = fmaxf(o.z, 0.f); o.w = fmaxf(o.w, 0.f);
            }
            if (HASR) {
                float4 rr = *(const float4*)&res[off + jj * 4];
                o.x += rr.x; o.y += rr.y; o.z += rr.z; o.w += rr.w;
            }
            *(float4*)&C[off + jj * 4] = o;
        }
    }
}

// ---------------- Flash attention (causal, fp32, online softmax) ----------------
// Grid: (T/64, NHEAD, BATCH). 256 threads = 8 warps; warp w owns query rows
// w*8..w*8+7 of the 64-row tile; lane owns key/value columns {lane, lane+32}.
// Q/K/V layout: [B, T, H*D] (GEMM output layout), head h at column offset h*64.
__global__ void __launch_bounds__(256) flash_attn(
    const float* __restrict__ Q, const float* __restrict__ Kp,
    const float* __restrict__ Vp, float* __restrict__ Op)
{
    extern __shared__ float sm[];
    float* sq  = sm;                 // [64][68]  q[row][d]
    float* sk  = sm + 64 * 68;       // [64][68]  k[key][d]
    float* svT = sm + 2 * 64 * 68;   // [64][68]  v transposed: svT[d][key]
    float* pb  = sm + 3 * 64 * 68;   // [64][64]  softmax probs, per-warp rows

    int qt = blockIdx.x, h = blockIdx.y, b = blockIdx.z;
    int tid = threadIdx.x, w = tid >> 5, lane = tid & 31;
    size_t base = ((size_t)b * SEQ) * N_EMBD + h * DHEAD;
    int q0 = qt * 64;

    // load Q tile (coalesced), padded stride 68 for conflict-free reads
    #pragma unroll
    for (int i = 0; i < 4; i++) {
        int f = tid + i * 256;
        int r = f >> 4, c4 = f & 15;
        *(float4*)&sq[r * 68 + c4 * 4] =
            *(const float4*)&Q[base + (size_t)(q0 + r) * N_EMBD + c4 * 4];
    }

    float m[8], l[8], acc[8][2];
    #pragma unroll
    for (int r = 0; r < 8; r++) {
        m[r] = -1e30f; l[r] = 0.f; acc[r][0] = 0.f; acc[r][1] = 0.f;
    }

    for (int kt = 0; kt <= qt; kt++) {
        int k0 = kt * 64;
        __syncthreads();  // all warps done with previous sk/svT
        #pragma unroll
        for (int i = 0; i < 4; i++) {
            int f = tid + i * 256;
            int r = f >> 4, c4 = f & 15;
            *(float4*)&sk[r * 68 + c4 * 4] =
                *(const float4*)&Kp[base + (size_t)(k0 + r) * N_EMBD + c4 * 4];
            float4 v4 = *(const float4*)&Vp[base + (size_t)(k0 + r) * N_EMBD + c4 * 4];
            svT[(c4 * 4 + 0) * 68 + r] = v4.x;
            svT[(c4 * 4 + 1) * 68 + r] = v4.y;
            svT[(c4 * 4 + 2) * 68 + r] = v4.z;
            svT[(c4 * 4 + 3) * 68 + r] = v4.w;
        }
        __syncthreads();

        // scores s[r][j] = q_row . k_col, j in {lane, lane+32}
        float s[8][2];
        #pragma unroll
        for (int r = 0; r < 8; r++) { s[r][0] = 0.f; s[r][1] = 0.f; }
        #pragma unroll
        for (int d4 = 0; d4 < 16; d4++) {
            float4 kv0 = *(const float4*)&sk[lane * 68 + d4 * 4];
            float4 kv1 = *(const float4*)&sk[(lane + 32) * 68 + d4 * 4];
            #pragma unroll
            for (int r = 0; r < 8; r++) {
                float4 q4 = *(const float4*)&sq[(w * 8 + r) * 68 + d4 * 4];
                s[r][0] = fmaf(q4.x, kv0.x, s[r][0]);
                s[r][0] = fmaf(q4.y, kv0.y, s[r][0]);
                s[r][0] = fmaf(q4.z, kv0.z, s[r][0]);
                s[r][0] = fmaf(q4.w, kv0.w, s[r][0]);
                s[r][1] = fmaf(q4.x, kv1.x, s[r][1]);
                s[r][1] = fmaf(q4.y, kv1.y, s[r][1]);
                s[r][1] = fmaf(q4.z, kv1.z, s[r][1]);
                s[r][1] = fmaf(q4.w, kv1.w, s[r][1]);
            }
        }

        bool diag = (kt == qt);
        #pragma unroll
        for (int r = 0; r < 8; r++) {
            int qg = q0 + w * 8 + r;
            float s0 = s[r][0] * 0.03125f;   // scale = C^-0.5 = 1/32
            float s1 = s[r][1] * 0.03125f;
            if (diag) {
                if (k0 + lane      > qg) s0 = -1e30f;
                if (k0 + lane + 32 > qg) s1 = -1e30f;
            }
            float mx = fmaxf(s0, s1);
            #pragma unroll
            for (int o = 16; o; o >>= 1)
                mx = fmaxf(mx, __shfl_xor_sync(0xffffffffu, mx, o));
            float mnew  = fmaxf(m[r], mx);
            float alpha = exp2f((m[r] - mnew) * LOG2E);
            float p0    = exp2f((s0 - mnew) * LOG2E);
            float p1    = exp2f((s1 - mnew) * LOG2E);
            float ps = p0 + p1;
            #pragma unroll
            for (int o = 16; o; o >>= 1)
                ps += __shfl_xor_sync(0xffffffffu, ps, o);
            l[r] = l[r] * alpha + ps;
            m[r] = mnew;
            acc[r][0] *= alpha;
            acc[r][1] *= alpha;
            pb[(w * 8 + r) * 64 + lane]      = p0;
            pb[(w * 8 + r) * 64 + lane + 32] = p1;
        }
        __syncwarp();  // pb is warp-private; order stores before loads

        // O[r][d] += sum_c p[r][c] * V[c][d], d in {lane, lane+32}
        #pragma unroll
        for (int c4 = 0; c4 < 16; c4++) {
            float4 v0 = *(const float4*)&svT[lane * 68 + c4 * 4];
            float4 v1 = *(const float4*)&svT[(lane + 32) * 68 + c4 * 4];
            #pragma unroll
            for (int r = 0; r < 8; r++) {
                float4 p4 = *(const float4*)&pb[(w * 8 + r) * 64 + c4 * 4];
                acc[r][0] = fmaf(p4.x, v0.x, acc[r][0]);
                acc[r][0] = fmaf(p4.y, v0.y, acc[r][0]);
                acc[r][0] = fmaf(p4.z, v0.z, acc[r][0]);
                acc[r][0] = fmaf(p4.w, v0.w, acc[r][0]);
                acc[r][1] = fmaf(p4.x, v1.x, acc[r][1]);
                acc[r][1] = fmaf(p4.y, v1.y, acc[r][1]);
                acc[r][1] = fmaf(p4.z, v1.z, acc[r][1]);
                acc[r][1] = fmaf(p4.w, v1.w, acc[r][1]);
            }
        }
    }

    #pragma unroll
    for (int r = 0; r < 8; r++) {
        int qg = q0 + w * 8 + r;
        float inv = 1.0f / l[r];
        Op[base + (size_t)qg * N_EMBD + lane]      = acc[r][0] * inv;
        Op[base + (size_t)qg * N_EMBD + lane + 32] = acc[r][1] * inv;
    }
}

// ---------------- launch ----------------
extern "C" void kernel_launch(void* const* d_in, const int* in_sizes, int n_in,
                              void* d_out, int out_size)
{
    (void)in_sizes; (void)n_in; (void)out_size;
    const float* x     = (const float*)d_in[0];
    const float* Wq    = (const float*)d_in[1];
    const float* Wk    = (const float*)d_in[2];
    const float* Wv    = (const float*)d_in[3];
    const float* Wproj = (const float*)d_in[4];
    const float* bproj = (const float*)d_in[5];
    const float* W1    = (const float*)d_in[6];
    const float* b1    = (const float*)d_in[7];
    const float* W2    = (const float*)d_in[8];
    const float* b2    = (const float*)d_in[9];
    const float* ln1w  = (const float*)d_in[10];
    const float* ln1b  = (const float*)d_in[11];
    const float* ln2w  = (const float*)d_in[12];
    const float* ln2b  = (const float*)d_in[13];
    float* out = (float*)d_out;

    float *h, *q, *k, *v, *attn, *ff;
    cudaGetSymbolAddress((void**)&h,    g_h);
    cudaGetSymbolAddress((void**)&q,    g_q);
    cudaGetSymbolAddress((void**)&k,    g_k);
    cudaGetSymbolAddress((void**)&v,    g_v);
    cudaGetSymbolAddress((void**)&attn, g_attn);
    cudaGetSymbolAddress((void**)&ff,   g_ff);

    const int FA_SMEM = (3 * 64 * 68 + 64 * 64) * 4;  // 68608 bytes
    cudaFuncSetAttribute(flash_attn,
                         cudaFuncAttributeMaxDynamicSharedMemorySize, FA_SMEM);

    dim3 blk(256);
    dim3 g1(N_EMBD / 128, MROWS / 128);   // (8, 32)
    dim3 g2(FFDIM / 128,  MROWS / 128);   // (32, 32)
    dim3 ga(SEQ / 64, NHEAD, BATCH);      // (32, 16, 2)

    // h1 = LN1(x)
    ln_kernel<<<MROWS, 256>>>(x, ln1w, ln1b, h);
    // q/k/v = h1 @ W{q,k,v}
    sgemm<0,0,0><<<g1, blk>>>(h, Wq, nullptr, nullptr, q, MROWS, N_EMBD, N_EMBD);
    sgemm<0,0,0><<<g1, blk>>>(h, Wk, nullptr, nullptr, k, MROWS, N_EMBD, N_EMBD);
    sgemm<0,0,0><<<g1, blk>>>(h, Wv, nullptr, nullptr, v, MROWS, N_EMBD, N_EMBD);
    // attn = causal softmax(q k^T / 32) v
    flash_attn<<<ga, 256, FA_SMEM>>>(q, k, v, attn);
    // out = x + attn @ Wproj + bproj
    sgemm<0,1,1><<<g1, blk>>>(attn, Wproj, bproj, x, out, MROWS, N_EMBD, N_EMBD);
    // h2 = LN2(out)
    ln_kernel<<<MROWS, 256>>>(out, ln2w, ln2b, h);
    // ff = relu(h2 @ W1 + b1)
    sgemm<1,1,0><<<g2, blk>>>(h, W1, b1, nullptr, ff, MROWS, FFDIM, N_EMBD);
    // out = out + ff @ W2 + b2
    sgemm<0,1,1><<<g1, blk>>>(ff, W2, b2, out, out, MROWS, N_EMBD, FFDIM);
}

// round 9
// speedup vs baseline: 1.5569x; 1.5569x over previous
#include <cuda_runtime.h>
#include <cuda_bf16.h>
#include <cstdint>
#include <math.h>

#define N_EMBD 1024
#define SEQ    2048
#define BATCH  2
#define NHEAD  16
#define DHEAD  64
#define FFDIM  4096
#define MROWS  (BATCH*SEQ)   // 4096
#define LOG2E  1.4426950408889634f

// ======================= scratch (__device__ globals) =======================
__device__ __nv_bfloat16 g_h_hi [(size_t)MROWS * N_EMBD];
__device__ __nv_bfloat16 g_h_lo [(size_t)MROWS * N_EMBD];
__device__ __nv_bfloat16 g_at_hi[(size_t)MROWS * N_EMBD];
__device__ __nv_bfloat16 g_at_lo[(size_t)MROWS * N_EMBD];
__device__ __nv_bfloat16 g_ff_hi[(size_t)MROWS * FFDIM];
__device__ __nv_bfloat16 g_ff_lo[(size_t)MROWS * FFDIM];
__device__ float g_q[(size_t)MROWS * N_EMBD];
__device__ float g_k[(size_t)MROWS * N_EMBD];
__device__ float g_v[(size_t)MROWS * N_EMBD];
// transposed+split weights: [N][K] layout (k-contiguous)
__device__ __nv_bfloat16 g_wq_hi[(size_t)N_EMBD * N_EMBD], g_wq_lo[(size_t)N_EMBD * N_EMBD];
__device__ __nv_bfloat16 g_wk_hi[(size_t)N_EMBD * N_EMBD], g_wk_lo[(size_t)N_EMBD * N_EMBD];
__device__ __nv_bfloat16 g_wv_hi[(size_t)N_EMBD * N_EMBD], g_wv_lo[(size_t)N_EMBD * N_EMBD];
__device__ __nv_bfloat16 g_wp_hi[(size_t)N_EMBD * N_EMBD], g_wp_lo[(size_t)N_EMBD * N_EMBD];
__device__ __nv_bfloat16 g_w1_hi[(size_t)FFDIM * N_EMBD], g_w1_lo[(size_t)FFDIM * N_EMBD];
__device__ __nv_bfloat16 g_w2_hi[(size_t)N_EMBD * FFDIM], g_w2_lo[(size_t)N_EMBD * FFDIM];

__device__ __forceinline__ void split_bf16(float v, __nv_bfloat16& hi, __nv_bfloat16& lo) {
    hi = __float2bfloat16(v);
    lo = __float2bfloat16(v - __bfloat162float(hi));
}

__device__ __forceinline__ uint32_t smem_u32(const void* p) {
    uint32_t a;
    asm("{ .reg .u64 t; cvta.to.shared.u64 t, %1; cvt.u32.u64 %0, t; }" : "=r"(a) : "l"(p));
    return a;
}

// ldmatrix x4: four 8x8 b16 matrices (family-portable, sm_75+)
__device__ __forceinline__ void ldsm4(uint32_t* r, uint32_t addr) {
    asm volatile("ldmatrix.sync.aligned.m8n8.x4.shared.b16 {%0,%1,%2,%3}, [%4];"
        : "=r"(r[0]), "=r"(r[1]), "=r"(r[2]), "=r"(r[3]) : "r"(addr));
}

// mma.sync m16n8k16 bf16 -> fp32 accum (family-portable, sm_80+)
__device__ __forceinline__ void mma16816(float* d, const uint32_t* a, uint32_t b0, uint32_t b1) {
    asm volatile(
        "mma.sync.aligned.m16n8k16.row.col.f32.bf16.bf16.f32 "
        "{%0,%1,%2,%3}, {%4,%5,%6,%7}, {%8,%9}, {%0,%1,%2,%3};"
        : "+f"(d[0]), "+f"(d[1]), "+f"(d[2]), "+f"(d[3])
        : "r"(a[0]), "r"(a[1]), "r"(a[2]), "r"(a[3]), "r"(b0), "r"(b1));
}

// ======================= weight transpose + split =======================
// W [K][N] fp32 -> Th/Tl [N][K] bf16.  block (32,8), grid (N/32, K/32)
__global__ void __launch_bounds__(256) tsplit(
    const float* __restrict__ W, __nv_bfloat16* __restrict__ Th,
    __nv_bfloat16* __restrict__ Tl, int K, int N)
{
    __shared__ float t[32][33];
    int k0 = blockIdx.y * 32, n0 = blockIdx.x * 32;
    int tx = threadIdx.x, ty = threadIdx.y;
    #pragma unroll
    for (int i = 0; i < 32; i += 8)
        t[ty + i][tx] = W[(size_t)(k0 + ty + i) * N + n0 + tx];
    __syncthreads();
    #pragma unroll
    for (int i = 0; i < 32; i += 8) {
        float v = t[tx][ty + i];
        __nv_bfloat16 hi, lo; split_bf16(v, hi, lo);
        size_t off = (size_t)(n0 + ty + i) * K + k0 + tx;
        Th[off] = hi; Tl[off] = lo;
    }
}

// ======================= LayerNorm (fused split output) =======================
__global__ void __launch_bounds__(256) ln_kernel(
    const float* __restrict__ x, const float* __restrict__ w,
    const float* __restrict__ b, __nv_bfloat16* __restrict__ Oh,
    __nv_bfloat16* __restrict__ Ol)
{
    int row = blockIdx.x;
    int tid = threadIdx.x;
    const float* xr = x + (size_t)row * N_EMBD;

    float4 xv = *(const float4*)(xr + tid * 4);
    float s  = xv.x + xv.y + xv.z + xv.w;
    float ss = xv.x*xv.x + xv.y*xv.y + xv.z*xv.z + xv.w*xv.w;
    #pragma unroll
    for (int o = 16; o; o >>= 1) {
        s  += __shfl_xor_sync(0xffffffffu, s,  o);
        ss += __shfl_xor_sync(0xffffffffu, ss, o);
    }
    __shared__ float sb[8], ssb[8];
    int wid = tid >> 5, lane = tid & 31;
    if (lane == 0) { sb[wid] = s; ssb[wid] = ss; }
    __syncthreads();
    if (wid == 0) {
        s  = (lane < 8) ? sb[lane]  : 0.f;
        ss = (lane < 8) ? ssb[lane] : 0.f;
        #pragma unroll
        for (int o = 4; o; o >>= 1) {
            s  += __shfl_xor_sync(0xffffffffu, s,  o);
            ss += __shfl_xor_sync(0xffffffffu, ss, o);
        }
        if (lane == 0) { sb[0] = s; ssb[0] = ss; }
    }
    __syncthreads();
    s = sb[0]; ss = ssb[0];

    float mu   = s * (1.0f / N_EMBD);
    float var  = ss * (1.0f / N_EMBD) - mu * mu;
    float rstd = rsqrtf(var + 1e-5f);

    float4 wv = *(const float4*)(w + tid * 4);
    float4 bv = *(const float4*)(b + tid * 4);
    float o0 = (xv.x - mu) * rstd * wv.x + bv.x;
    float o1 = (xv.y - mu) * rstd * wv.y + bv.y;
    float o2 = (xv.z - mu) * rstd * wv.z + bv.z;
    float o3 = (xv.w - mu) * rstd * wv.w + bv.w;
    __nv_bfloat16 h0,l0,h1,l1,h2,l2,h3,l3;
    split_bf16(o0,h0,l0); split_bf16(o1,h1,l1);
    split_bf16(o2,h2,l2); split_bf16(o3,h3,l3);
    size_t off = (size_t)row * N_EMBD + tid * 4;
    *(__nv_bfloat162*)&Oh[off]     = __nv_bfloat162(h0, h1);
    *(__nv_bfloat162*)&Oh[off + 2] = __nv_bfloat162(h2, h3);
    *(__nv_bfloat162*)&Ol[off]     = __nv_bfloat162(l0, l1);
    *(__nv_bfloat162*)&Ol[off + 2] = __nv_bfloat162(l2, l3);
}

// ======================= mma.sync GEMM (bf16x3 emulated fp32) =======================
// C[M,N] = epi( A[M,K] @ B^T )  A: hi/lo bf16 [M][K], B^T: hi/lo bf16 [N][K].
// D = Ah*Bh + Ah*Bl + Al*Bh (fp32 accum in mma).
// 128x128 tile, BK=32, 256 threads, 8 warps in 4(m) x 2(n); warp = 32x64.
// EPI: 0 = fp32 store; 1 = fp32 d+bias+res; 2 = relu(d+bias) -> bf16 hi/lo split
#define AST 40                     // smem row stride in bf16 (80 bytes)
#define TILE_BF (128 * AST)        // 5120 bf16 per tile
template<int EPI>
__global__ void __launch_bounds__(256) tgemm(
    const __nv_bfloat16* __restrict__ Ah, const __nv_bfloat16* __restrict__ Al,
    const __nv_bfloat16* __restrict__ Bh, const __nv_bfloat16* __restrict__ Bl,
    const float* __restrict__ bias, const float* __restrict__ res,
    float* __restrict__ Cf, __nv_bfloat16* __restrict__ Ch,
    __nv_bfloat16* __restrict__ Cl, int M, int N, int K)
{
    __shared__ __nv_bfloat16 smem[4 * TILE_BF];   // Ah | Al | Bh | Bl (40 KB)
    __nv_bfloat16* sAh = smem;
    __nv_bfloat16* sAl = smem + TILE_BF;
    __nv_bfloat16* sBh = smem + 2 * TILE_BF;
    __nv_bfloat16* sBl = smem + 3 * TILE_BF;

    int tid = threadIdx.x, lane = tid & 31, wid = tid >> 5;
    int wm = wid & 3, wn = wid >> 2;            // warp tile: rows wm*32, cols wn*64
    int m0 = blockIdx.y * 128, n0 = blockIdx.x * 128;

    float acc[2][8][4];
    #pragma unroll
    for (int mi = 0; mi < 2; mi++)
        #pragma unroll
        for (int ni = 0; ni < 8; ni++)
            #pragma unroll
            for (int j = 0; j < 4; j++) acc[mi][ni][j] = 0.f;

    uint32_t sb = smem_u32(smem);
    int lrow = lane & 15, lcol = lane >> 4;     // ldmatrix per-lane address pattern
    // byte offsets within a tile for this lane's ldmatrix base
    uint32_t aoff = ((uint32_t)(wm * 32 + lrow) * AST + lcol * 8) * 2;
    uint32_t boff = ((uint32_t)(wn * 64 + lrow) * AST + lcol * 8) * 2;
    const uint32_t T = TILE_BF * 2;             // tile size in bytes

    int nchunk = K >> 5;
    for (int ch = 0; ch < nchunk; ch++) {
        int k0 = ch << 5;
        // fill: each tile is 128 rows x 64B = 512 uint4; 2 per thread per tile
        #pragma unroll
        for (int i = 0; i < 2; i++) {
            int g = tid + i * 256;
            int r = g >> 2, c = g & 3;
            size_t gA = (size_t)(m0 + r) * K + k0 + c * 8;
            size_t gB = (size_t)(n0 + r) * K + k0 + c * 8;
            int so = r * AST + c * 8;
            *(uint4*)&sAh[so] = *(const uint4*)&Ah[gA];
            *(uint4*)&sAl[so] = *(const uint4*)&Al[gA];
            *(uint4*)&sBh[so] = *(const uint4*)&Bh[gB];
            *(uint4*)&sBl[so] = *(const uint4*)&Bl[gB];
        }
        __syncthreads();

        #pragma unroll
        for (int kk = 0; kk < 2; kk++) {
            uint32_t kb = kk * 32;              // 16 bf16 = 32 bytes
            uint32_t ah[2][4], al[2][4], bh[4][4], bl[4][4];
            #pragma unroll
            for (int mi = 0; mi < 2; mi++) {
                uint32_t o = aoff + mi * (16 * AST * 2) + kb;
                ldsm4(ah[mi], sb + o);          // sAh
                ldsm4(al[mi], sb + T + o);      // sAl
            }
            #pragma unroll
            for (int nj = 0; nj < 4; nj++) {
                uint32_t o = boff + nj * (16 * AST * 2) + kb;
                ldsm4(bh[nj], sb + 2 * T + o);  // sBh
                ldsm4(bl[nj], sb + 3 * T + o);  // sBl
            }
            #pragma unroll
            for (int mi = 0; mi < 2; mi++)
                #pragma unroll
                for (int ni = 0; ni < 8; ni++) {
                    int nj = ni >> 1, sel = ni & 1;
                    mma16816(acc[mi][ni], ah[mi], bh[nj][sel], bh[nj][sel + 2]);
                    mma16816(acc[mi][ni], ah[mi], bl[nj][sel], bl[nj][sel + 2]);
                    mma16816(acc[mi][ni], al[mi], bh[nj][sel], bh[nj][sel + 2]);
                }
        }
        __syncthreads();
    }

    // epilogue: d0,d1 -> (row, col..col+1); d2,d3 -> (row+8, col..col+1)
    int r_base = m0 + wm * 32 + (lane >> 2);
    int c_base = n0 + wn * 64 + (lane & 3) * 2;
    #pragma unroll
    for (int mi = 0; mi < 2; mi++)
        #pragma unroll
        for (int ni = 0; ni < 8; ni++) {
            int col = c_base + ni * 8;
            #pragma unroll
            for (int h = 0; h < 2; h++) {
                int row = r_base + mi * 16 + h * 8;
                float d0 = acc[mi][ni][h * 2], d1 = acc[mi][ni][h * 2 + 1];
                size_t off = (size_t)row * N + col;
                if (EPI == 0) {
                    Cf[off] = d0; Cf[off + 1] = d1;
                } else if (EPI == 1) {
                    Cf[off]     = d0 + bias[col]     + res[off];
                    Cf[off + 1] = d1 + bias[col + 1] + res[off + 1];
                } else {
                    float v0 = fmaxf(d0 + bias[col],     0.f);
                    float v1 = fmaxf(d1 + bias[col + 1], 0.f);
                    __nv_bfloat16 h0, l0, h1, l1;
                    split_bf16(v0, h0, l0);
                    split_bf16(v1, h1, l1);
                    *(__nv_bfloat162*)&Ch[off] = __nv_bfloat162(h0, h1);
                    *(__nv_bfloat162*)&Cl[off] = __nv_bfloat162(l0, l1);
                }
            }
        }
}

// ======================= Flash attention (causal, fp32, split output) =======================
__global__ void __launch_bounds__(256) flash_attn(
    const float* __restrict__ Q, const float* __restrict__ Kp,
    const float* __restrict__ Vp, __nv_bfloat16* __restrict__ Oh,
    __nv_bfloat16* __restrict__ Ol)
{
    extern __shared__ float sm[];
    float* sq  = sm;
    float* sk  = sm + 64 * 68;
    float* svT = sm + 2 * 64 * 68;
    float* pb  = sm + 3 * 64 * 68;

    int qt = blockIdx.x, h = blockIdx.y, b = blockIdx.z;
    int tid = threadIdx.x, w = tid >> 5, lane = tid & 31;
    size_t base = ((size_t)b * SEQ) * N_EMBD + h * DHEAD;
    int q0 = qt * 64;

    #pragma unroll
    for (int i = 0; i < 4; i++) {
        int f = tid + i * 256;
        int r = f >> 4, c4 = f & 15;
        *(float4*)&sq[r * 68 + c4 * 4] =
            *(const float4*)&Q[base + (size_t)(q0 + r) * N_EMBD + c4 * 4];
    }

    float m[8], l[8], acc[8][2];
    #pragma unroll
    for (int r = 0; r < 8; r++) {
        m[r] = -1e30f; l[r] = 0.f; acc[r][0] = 0.f; acc[r][1] = 0.f;
    }

    for (int kt = 0; kt <= qt; kt++) {
        int k0 = kt * 64;
        __syncthreads();
        #pragma unroll
        for (int i = 0; i < 4; i++) {
            int f = tid + i * 256;
            int r = f >> 4, c4 = f & 15;
            *(float4*)&sk[r * 68 + c4 * 4] =
                *(const float4*)&Kp[base + (size_t)(k0 + r) * N_EMBD + c4 * 4];
            float4 v4 = *(const float4*)&Vp[base + (size_t)(k0 + r) * N_EMBD + c4 * 4];
            svT[(c4 * 4 + 0) * 68 + r] = v4.x;
            svT[(c4 * 4 + 1) * 68 + r] = v4.y;
            svT[(c4 * 4 + 2) * 68 + r] = v4.z;
            svT[(c4 * 4 + 3) * 68 + r] = v4.w;
        }
        __syncthreads();

        float s[8][2];
        #pragma unroll
        for (int r = 0; r < 8; r++) { s[r][0] = 0.f; s[r][1] = 0.f; }
        #pragma unroll
        for (int d4 = 0; d4 < 16; d4++) {
            float4 kv0 = *(const float4*)&sk[lane * 68 + d4 * 4];
            float4 kv1 = *(const float4*)&sk[(lane + 32) * 68 + d4 * 4];
            #pragma unroll
            for (int r = 0; r < 8; r++) {
                float4 q4 = *(const float4*)&sq[(w * 8 + r) * 68 + d4 * 4];
                s[r][0] = fmaf(q4.x, kv0.x, s[r][0]);
                s[r][0] = fmaf(q4.y, kv0.y, s[r][0]);
                s[r][0] = fmaf(q4.z, kv0.z, s[r][0]);
                s[r][0] = fmaf(q4.w, kv0.w, s[r][0]);
                s[r][1] = fmaf(q4.x, kv1.x, s[r][1]);
                s[r][1] = fmaf(q4.y, kv1.y, s[r][1]);
                s[r][1] = fmaf(q4.z, kv1.z, s[r][1]);
                s[r][1] = fmaf(q4.w, kv1.w, s[r][1]);
            }
        }

        bool diag = (kt == qt);
        #pragma unroll
        for (int r = 0; r < 8; r++) {
            int qg = q0 + w * 8 + r;
            float s0 = s[r][0] * 0.03125f;
            float s1 = s[r][1] * 0.03125f;
            if (diag) {
                if (k0 + lane      > qg) s0 = -1e30f;
                if (k0 + lane + 32 > qg) s1 = -1e30f;
            }
            float mx = fmaxf(s0, s1);
            #pragma unroll
            for (int o = 16; o; o >>= 1)
                mx = fmaxf(mx, __shfl_xor_sync(0xffffffffu, mx, o));
            float mnew  = fmaxf(m[r], mx);
            float alpha = exp2f((m[r] - mnew) * LOG2E);
            float p0    = exp2f((s0 - mnew) * LOG2E);
            float p1    = exp2f((s1 - mnew) * LOG2E);
            float ps = p0 + p1;
            #pragma unroll
            for (int o = 16; o; o >>= 1)
                ps += __shfl_xor_sync(0xffffffffu, ps, o);
            l[r] = l[r] * alpha + ps;
            m[r] = mnew;
            acc[r][0] *= alpha;
            acc[r][1] *= alpha;
            pb[(w * 8 + r) * 64 + lane]      = p0;
            pb[(w * 8 + r) * 64 + lane + 32] = p1;
        }
        __syncwarp();

        #pragma unroll
        for (int c4 = 0; c4 < 16; c4++) {
            float4 v0 = *(const float4*)&svT[lane * 68 + c4 * 4];
            float4 v1 = *(const float4*)&svT[(lane + 32) * 68 + c4 * 4];
            #pragma unroll
            for (int r = 0; r < 8; r++) {
                float4 p4 = *(const float4*)&pb[(w * 8 + r) * 64 + c4 * 4];
                acc[r][0] = fmaf(p4.x, v0.x, acc[r][0]);
                acc[r][0] = fmaf(p4.y, v0.y, acc[r][0]);
                acc[r][0] = fmaf(p4.z, v0.z, acc[r][0]);
                acc[r][0] = fmaf(p4.w, v0.w, acc[r][0]);
                acc[r][1] = fmaf(p4.x, v1.x, acc[r][1]);
                acc[r][1] = fmaf(p4.y, v1.y, acc[r][1]);
                acc[r][1] = fmaf(p4.z, v1.z, acc[r][1]);
                acc[r][1] = fmaf(p4.w, v1.w, acc[r][1]);
            }
        }
    }

    #pragma unroll
    for (int r = 0; r < 8; r++) {
        int qg = q0 + w * 8 + r;
        float inv = 1.0f / l[r];
        float v0 = acc[r][0] * inv;
        float v1 = acc[r][1] * inv;
        __nv_bfloat16 h0, l0, h1, l1;
        split_bf16(v0, h0, l0);
        split_bf16(v1, l1, l1);   // placeholder overwritten below
        split_bf16(v1, h1, l1);
        size_t o0 = base + (size_t)qg * N_EMBD + lane;
        Oh[o0]      = h0;  Ol[o0]      = l0;
        Oh[o0 + 32] = h1;  Ol[o0 + 32] = l1;
    }
}

// ======================= launch =======================
extern "C" void kernel_launch(void* const* d_in, const int* in_sizes, int n_in,
                              void* d_out, int out_size)
{
    (void)in_sizes; (void)n_in; (void)out_size;
    const float* x     = (const float*)d_in[0];
    const float* Wq    = (const float*)d_in[1];
    const float* Wk    = (const float*)d_in[2];
    const float* Wv    = (const float*)d_in[3];
    const float* Wproj = (const float*)d_in[4];
    const float* bproj = (const float*)d_in[5];
    const float* W1    = (const float*)d_in[6];
    const float* b1    = (const float*)d_in[7];
    const float* W2    = (const float*)d_in[8];
    const float* b2    = (const float*)d_in[9];
    const float* ln1w  = (const float*)d_in[10];
    const float* ln1b  = (const float*)d_in[11];
    const float* ln2w  = (const float*)d_in[12];
    const float* ln2b  = (const float*)d_in[13];
    float* out = (float*)d_out;

    __nv_bfloat16 *h_hi, *h_lo, *at_hi, *at_lo, *ff_hi, *ff_lo;
    __nv_bfloat16 *wq_hi, *wq_lo, *wk_hi, *wk_lo, *wv_hi, *wv_lo, *wp_hi, *wp_lo;
    __nv_bfloat16 *w1_hi, *w1_lo, *w2_hi, *w2_lo;
    float *q, *k, *v;
    cudaGetSymbolAddress((void**)&h_hi,  g_h_hi);   cudaGetSymbolAddress((void**)&h_lo,  g_h_lo);
    cudaGetSymbolAddress((void**)&at_hi, g_at_hi);  cudaGetSymbolAddress((void**)&at_lo, g_at_lo);
    cudaGetSymbolAddress((void**)&ff_hi, g_ff_hi);  cudaGetSymbolAddress((void**)&ff_lo, g_ff_lo);
    cudaGetSymbolAddress((void**)&wq_hi, g_wq_hi);  cudaGetSymbolAddress((void**)&wq_lo, g_wq_lo);
    cudaGetSymbolAddress((void**)&wk_hi, g_wk_hi);  cudaGetSymbolAddress((void**)&wk_lo, g_wk_lo);
    cudaGetSymbolAddress((void**)&wv_hi, g_wv_hi);  cudaGetSymbolAddress((void**)&wv_lo, g_wv_lo);
    cudaGetSymbolAddress((void**)&wp_hi, g_wp_hi);  cudaGetSymbolAddress((void**)&wp_lo, g_wp_lo);
    cudaGetSymbolAddress((void**)&w1_hi, g_w1_hi);  cudaGetSymbolAddress((void**)&w1_lo, g_w1_lo);
    cudaGetSymbolAddress((void**)&w2_hi, g_w2_hi);  cudaGetSymbolAddress((void**)&w2_lo, g_w2_lo);
    cudaGetSymbolAddress((void**)&q, g_q);
    cudaGetSymbolAddress((void**)&k, g_k);
    cudaGetSymbolAddress((void**)&v, g_v);

    const int FA_SMEM = (3 * 64 * 68 + 64 * 64) * 4;
    cudaFuncSetAttribute(flash_attn, cudaFuncAttributeMaxDynamicSharedMemorySize, FA_SMEM);

    dim3 tsb(32, 8);
    // weight transpose+split: W[K][N] -> [N][K]
    tsplit<<<dim3(N_EMBD / 32, N_EMBD / 32), tsb>>>(Wq,    wq_hi, wq_lo, N_EMBD, N_EMBD);
    tsplit<<<dim3(N_EMBD / 32, N_EMBD / 32), tsb>>>(Wk,    wk_hi, wk_lo, N_EMBD, N_EMBD);
    tsplit<<<dim3(N_EMBD / 32, N_EMBD / 32), tsb>>>(Wv,    wv_hi, wv_lo, N_EMBD, N_EMBD);
    tsplit<<<dim3(N_EMBD / 32, N_EMBD / 32), tsb>>>(Wproj, wp_hi, wp_lo, N_EMBD, N_EMBD);
    tsplit<<<dim3(FFDIM / 32,  N_EMBD / 32), tsb>>>(W1,    w1_hi, w1_lo, N_EMBD, FFDIM);
    tsplit<<<dim3(N_EMBD / 32, FFDIM / 32),  tsb>>>(W2,    w2_hi, w2_lo, FFDIM, N_EMBD);

    dim3 g1(N_EMBD / 128, MROWS / 128);   // (8, 32)
    dim3 g2(FFDIM / 128,  MROWS / 128);   // (32, 32)
    dim3 ga(SEQ / 64, NHEAD, BATCH);

    // h = LN1(x)   (split bf16)
    ln_kernel<<<MROWS, 256>>>(x, ln1w, ln1b, h_hi, h_lo);
    // q/k/v = h @ W{q,k,v}   (fp32 out)
    tgemm<0><<<g1, 256>>>(h_hi, h_lo, wq_hi, wq_lo, nullptr, nullptr,
                          q, nullptr, nullptr, MROWS, N_EMBD, N_EMBD);
    tgemm<0><<<g1, 256>>>(h_hi, h_lo, wk_hi, wk_lo, nullptr, nullptr,
                          k, nullptr, nullptr, MROWS, N_EMBD, N_EMBD);
    tgemm<0><<<g1, 256>>>(h_hi, h_lo, wv_hi, wv_lo, nullptr, nullptr,
                          v, nullptr, nullptr, MROWS, N_EMBD, N_EMBD);
    // attn (split bf16 out)
    flash_attn<<<ga, 256, FA_SMEM>>>(q, k, v, at_hi, at_lo);
    // out = x + attn @ Wproj + bproj
    tgemm<1><<<g1, 256>>>(at_hi, at_lo, wp_hi, wp_lo, bproj, x,
                          out, nullptr, nullptr, MROWS, N_EMBD, N_EMBD);
    // h = LN2(out)
    ln_kernel<<<MROWS, 256>>>(out, ln2w, ln2b, h_hi, h_lo);
    // ff = relu(h @ W1 + b1)   (split bf16 out)
    tgemm<2><<<g2, 256>>>(h_hi, h_lo, w1_hi, w1_lo, b1, nullptr,
                          nullptr, ff_hi, ff_lo, MROWS, FFDIM, N_EMBD);
    // out = out + ff @ W2 + b2
    tgemm<1><<<g1, 256>>>(ff_hi, ff_lo, w2_hi, w2_lo, b2, out,
                          out, nullptr, nullptr, MROWS, N_EMBD, FFDIM);
}

// round 17
// speedup vs baseline: 2.0571x; 1.3213x over previous
#include <cuda_runtime.h>
#include <cuda_bf16.h>
#include <cstdint>
#include <math.h>

#define N_EMBD 1024
#define SEQ    2048
#define BATCH  2
#define NHEAD  16
#define DHEAD  64
#define FFDIM  4096
#define MROWS  (BATCH*SEQ)   // 4096
#define LOG2E  1.4426950408889634f

// ======================= scratch (__device__ globals) =======================
__device__ __nv_bfloat16 g_h_hi [(size_t)MROWS * N_EMBD];
__device__ __nv_bfloat16 g_h_lo [(size_t)MROWS * N_EMBD];
__device__ __nv_bfloat16 g_at_hi[(size_t)MROWS * N_EMBD];
__device__ __nv_bfloat16 g_at_lo[(size_t)MROWS * N_EMBD];
__device__ __nv_bfloat16 g_ff_hi[(size_t)MROWS * FFDIM];
__device__ __nv_bfloat16 g_ff_lo[(size_t)MROWS * FFDIM];
__device__ float g_qkv[(size_t)MROWS * 3 * N_EMBD];
// transposed+split weights: [N][K] (k-contiguous). QKV concatenated along N.
__device__ __nv_bfloat16 g_wqkv_hi[(size_t)3 * N_EMBD * N_EMBD], g_wqkv_lo[(size_t)3 * N_EMBD * N_EMBD];
__device__ __nv_bfloat16 g_wp_hi[(size_t)N_EMBD * N_EMBD], g_wp_lo[(size_t)N_EMBD * N_EMBD];
__device__ __nv_bfloat16 g_w1_hi[(size_t)FFDIM * N_EMBD], g_w1_lo[(size_t)FFDIM * N_EMBD];
__device__ __nv_bfloat16 g_w2_hi[(size_t)N_EMBD * FFDIM], g_w2_lo[(size_t)N_EMBD * FFDIM];

__device__ __forceinline__ void split_bf16(float v, __nv_bfloat16& hi, __nv_bfloat16& lo) {
    hi = __float2bfloat16(v);
    lo = __float2bfloat16(v - __bfloat162float(hi));
}

__device__ __forceinline__ uint32_t smem_u32(const void* p) {
    uint32_t a;
    asm("{ .reg .u64 t; cvta.to.shared.u64 t, %1; cvt.u32.u64 %0, t; }" : "=r"(a) : "l"(p));
    return a;
}

__device__ __forceinline__ void ldsm4(uint32_t* r, uint32_t addr) {
    asm volatile("ldmatrix.sync.aligned.m8n8.x4.shared.b16 {%0,%1,%2,%3}, [%4];"
        : "=r"(r[0]), "=r"(r[1]), "=r"(r[2]), "=r"(r[3]) : "r"(addr));
}
__device__ __forceinline__ void ldsm4t(uint32_t* r, uint32_t addr) {
    asm volatile("ldmatrix.sync.aligned.m8n8.x4.trans.shared.b16 {%0,%1,%2,%3}, [%4];"
        : "=r"(r[0]), "=r"(r[1]), "=r"(r[2]), "=r"(r[3]) : "r"(addr));
}

__device__ __forceinline__ void mma16816(float* d, const uint32_t* a, uint32_t b0, uint32_t b1) {
    asm volatile(
        "mma.sync.aligned.m16n8k16.row.col.f32.bf16.bf16.f32 "
        "{%0,%1,%2,%3}, {%4,%5,%6,%7}, {%8,%9}, {%0,%1,%2,%3};"
        : "+f"(d[0]), "+f"(d[1]), "+f"(d[2]), "+f"(d[3])
        : "r"(a[0]), "r"(a[1]), "r"(a[2]), "r"(a[3]), "r"(b0), "r"(b1));
}

__device__ __forceinline__ void cp16(uint32_t saddr, const void* g) {
    asm volatile("cp.async.cg.shared.global [%0], [%1], 16;" :: "r"(saddr), "l"(g) : "memory");
}
__device__ __forceinline__ void cp_commit() {
    asm volatile("cp.async.commit_group;" ::: "memory");
}
template<int N> __device__ __forceinline__ void cp_wait() {
    asm volatile("cp.async.wait_group %0;" :: "n"(N) : "memory");
}

// pack two floats into bf16x2 hi + residual lo words
__device__ __forceinline__ void pack_split2(float a, float b, uint32_t& hi, uint32_t& lo) {
    __nv_bfloat16 ah = __float2bfloat16(a), bh = __float2bfloat16(b);
    __nv_bfloat16 al = __float2bfloat16(a - __bfloat162float(ah));
    __nv_bfloat16 bl = __float2bfloat16(b - __bfloat162float(bh));
    __nv_bfloat162 H(ah, bh), L(al, bl);
    hi = *reinterpret_cast<uint32_t*>(&H);
    lo = *reinterpret_cast<uint32_t*>(&L);
}

// ======================= weight transpose + split =======================
__global__ void __launch_bounds__(256) tsplit(
    const float* __restrict__ W, __nv_bfloat16* __restrict__ Th,
    __nv_bfloat16* __restrict__ Tl, int K, int N)
{
    __shared__ float t[32][33];
    int k0 = blockIdx.y * 32, n0 = blockIdx.x * 32;
    int tx = threadIdx.x, ty = threadIdx.y;
    #pragma unroll
    for (int i = 0; i < 32; i += 8)
        t[ty + i][tx] = W[(size_t)(k0 + ty + i) * N + n0 + tx];
    __syncthreads();
    #pragma unroll
    for (int i = 0; i < 32; i += 8) {
        float v = t[tx][ty + i];
        __nv_bfloat16 hi, lo; split_bf16(v, hi, lo);
        size_t off = (size_t)(n0 + ty + i) * K + k0 + tx;
        Th[off] = hi; Tl[off] = lo;
    }
}

// ======================= LayerNorm (fused split output) =======================
__global__ void __launch_bounds__(256) ln_kernel(
    const float* __restrict__ x, const float* __restrict__ w,
    const float* __restrict__ b, __nv_bfloat16* __restrict__ Oh,
    __nv_bfloat16* __restrict__ Ol)
{
    int row = blockIdx.x;
    int tid = threadIdx.x;
    const float* xr = x + (size_t)row * N_EMBD;

    float4 xv = *(const float4*)(xr + tid * 4);
    float s  = xv.x + xv.y + xv.z + xv.w;
    float ss = xv.x*xv.x + xv.y*xv.y + xv.z*xv.z + xv.w*xv.w;
    #pragma unroll
    for (int o = 16; o; o >>= 1) {
        s  += __shfl_xor_sync(0xffffffffu, s,  o);
        ss += __shfl_xor_sync(0xffffffffu, ss, o);
    }
    __shared__ float sb[8], ssb[8];
    int wid = tid >> 5, lane = tid & 31;
    if (lane == 0) { sb[wid] = s; ssb[wid] = ss; }
    __syncthreads();
    if (wid == 0) {
        s  = (lane < 8) ? sb[lane]  : 0.f;
        ss = (lane < 8) ? ssb[lane] : 0.f;
        #pragma unroll
        for (int o = 4; o; o >>= 1) {
            s  += __shfl_xor_sync(0xffffffffu, s,  o);
            ss += __shfl_xor_sync(0xffffffffu, ss, o);
        }
        if (lane == 0) { sb[0] = s; ssb[0] = ss; }
    }
    __syncthreads();
    s = sb[0]; ss = ssb[0];

    float mu   = s * (1.0f / N_EMBD);
    float var  = ss * (1.0f / N_EMBD) - mu * mu;
    float rstd = rsqrtf(var + 1e-5f);

    float4 wv = *(const float4*)(w + tid * 4);
    float4 bv = *(const float4*)(b + tid * 4);
    float o0 = (xv.x - mu) * rstd * wv.x + bv.x;
    float o1 = (xv.y - mu) * rstd * wv.y + bv.y;
    float o2 = (xv.z - mu) * rstd * wv.z + bv.z;
    float o3 = (xv.w - mu) * rstd * wv.w + bv.w;
    __nv_bfloat16 h0,l0,h1,l1,h2,l2,h3,l3;
    split_bf16(o0,h0,l0); split_bf16(o1,h1,l1);
    split_bf16(o2,h2,l2); split_bf16(o3,h3,l3);
    size_t off = (size_t)row * N_EMBD + tid * 4;
    *(__nv_bfloat162*)&Oh[off]     = __nv_bfloat162(h0, h1);
    *(__nv_bfloat162*)&Oh[off + 2] = __nv_bfloat162(h2, h3);
    *(__nv_bfloat162*)&Ol[off]     = __nv_bfloat162(l0, l1);
    *(__nv_bfloat162*)&Ol[off + 2] = __nv_bfloat162(l2, l3);
}

// ======================= mma.sync GEMM, cp.async double-buffered =======================
// C[M,N] = epi( A[M,K] @ B^T )  bf16x3: D = Ah*Bh + Ah*Bl + Al*Bh.
// 128x128 tile, BK=32, 256 threads, 8 warps 4(m) x 2(n).
// EPI: 0 fp32; 1 fp32 d+bias+res; 2 relu(d+bias) -> bf16 hi/lo
#define AST 40                     // smem row stride in bf16 (80B, 16B-aligned)
#define TILE_B (128 * AST * 2)     // 10240 bytes per tile
#define STAGE_B (4 * TILE_B)       // 40960 bytes per stage
#define TG_SMEM (2 * STAGE_B)      // 81920 bytes
template<int EPI>
__global__ void __launch_bounds__(256) tgemm(
    const __nv_bfloat16* __restrict__ Ah, const __nv_bfloat16* __restrict__ Al,
    const __nv_bfloat16* __restrict__ Bh, const __nv_bfloat16* __restrict__ Bl,
    const float* __restrict__ bias, const float* __restrict__ res,
    float* __restrict__ Cf, __nv_bfloat16* __restrict__ Ch,
    __nv_bfloat16* __restrict__ Cl, int M, int N, int K)
{
    extern __shared__ __nv_bfloat16 ds[];
    uint32_t sb0 = smem_u32(ds);

    int tid = threadIdx.x, lane = tid & 31, wid = tid >> 5;
    int wm = wid & 3, wn = wid >> 2;
    int m0 = blockIdx.y * 128, n0 = blockIdx.x * 128;

    float acc[2][8][4];
    #pragma unroll
    for (int mi = 0; mi < 2; mi++)
        #pragma unroll
        for (int ni = 0; ni < 8; ni++)
            #pragma unroll
            for (int j = 0; j < 4; j++) acc[mi][ni][j] = 0.f;

    int lrow = lane & 15, lcol = lane >> 4;
    uint32_t aoff = ((uint32_t)(wm * 32 + lrow) * AST + lcol * 8) * 2;
    uint32_t boff = ((uint32_t)(wn * 64 + lrow) * AST + lcol * 8) * 2;

    // fill address pattern: 2 x (row, 16B-col) per thread per tile
    int fr0 = tid >> 2,          fc0 = tid & 3;
    int fr1 = (tid + 256) >> 2,  fc1 = (tid + 256) & 3;
    uint32_t so0 = (uint32_t)(fr0 * AST + fc0 * 8) * 2;
    uint32_t so1 = (uint32_t)(fr1 * AST + fc1 * 8) * 2;

    int nchunk = K >> 5;

    auto prefetch = [&](int ch) {
        uint32_t base = sb0 + (uint32_t)(ch & 1) * STAGE_B;
        int k0 = ch << 5;
        size_t gA0 = (size_t)(m0 + fr0) * K + k0 + fc0 * 8;
        size_t gA1 = (size_t)(m0 + fr1) * K + k0 + fc1 * 8;
        size_t gB0 = (size_t)(n0 + fr0) * K + k0 + fc0 * 8;
        size_t gB1 = (size_t)(n0 + fr1) * K + k0 + fc1 * 8;
        cp16(base + so0,              Ah + gA0);
        cp16(base + so1,              Ah + gA1);
        cp16(base + TILE_B + so0,     Al + gA0);
        cp16(base + TILE_B + so1,     Al + gA1);
        cp16(base + 2 * TILE_B + so0, Bh + gB0);
        cp16(base + 2 * TILE_B + so1, Bh + gB1);
        cp16(base + 3 * TILE_B + so0, Bl + gB0);
        cp16(base + 3 * TILE_B + so1, Bl + gB1);
        cp_commit();
    };

    prefetch(0);
    for (int ch = 0; ch < nchunk; ch++) {
        if (ch + 1 < nchunk) { prefetch(ch + 1); cp_wait<1>(); }
        else cp_wait<0>();
        __syncthreads();

        uint32_t sbase = sb0 + (uint32_t)(ch & 1) * STAGE_B;
        #pragma unroll
        for (int kk = 0; kk < 2; kk++) {
            uint32_t kb = kk * 32;
            uint32_t ah[2][4], al[2][4], bh[4][4], bl[4][4];
            #pragma unroll
            for (int mi = 0; mi < 2; mi++) {
                uint32_t o = aoff + mi * (16 * AST * 2) + kb;
                ldsm4(ah[mi], sbase + o);
                ldsm4(al[mi], sbase + TILE_B + o);
            }
            #pragma unroll
            for (int nj = 0; nj < 4; nj++) {
                uint32_t o = boff + nj * (16 * AST * 2) + kb;
                ldsm4(bh[nj], sbase + 2 * TILE_B + o);
                ldsm4(bl[nj], sbase + 3 * TILE_B + o);
            }
            #pragma unroll
            for (int mi = 0; mi < 2; mi++)
                #pragma unroll
                for (int ni = 0; ni < 8; ni++) {
                    int nj = ni >> 1, sel = ni & 1;
                    mma16816(acc[mi][ni], ah[mi], bh[nj][sel], bh[nj][sel + 2]);
                    mma16816(acc[mi][ni], ah[mi], bl[nj][sel], bl[nj][sel + 2]);
                    mma16816(acc[mi][ni], al[mi], bh[nj][sel], bh[nj][sel + 2]);
                }
        }
        __syncthreads();
    }

    int r_base = m0 + wm * 32 + (lane >> 2);
    int c_base = n0 + wn * 64 + (lane & 3) * 2;
    #pragma unroll
    for (int mi = 0; mi < 2; mi++)
        #pragma unroll
        for (int ni = 0; ni < 8; ni++) {
            int col = c_base + ni * 8;
            #pragma unroll
            for (int h = 0; h < 2; h++) {
                int row = r_base + mi * 16 + h * 8;
                float d0 = acc[mi][ni][h * 2], d1 = acc[mi][ni][h * 2 + 1];
                size_t off = (size_t)row * N + col;
                if (EPI == 0) {
                    Cf[off] = d0; Cf[off + 1] = d1;
                } else if (EPI == 1) {
                    Cf[off]     = d0 + bias[col]     + res[off];
                    Cf[off + 1] = d1 + bias[col + 1] + res[off + 1];
                } else {
                    float v0 = fmaxf(d0 + bias[col],     0.f);
                    float v1 = fmaxf(d1 + bias[col + 1], 0.f);
                    __nv_bfloat16 h0, l0, h1, l1;
                    split_bf16(v0, h0, l0);
                    split_bf16(v1, h1, l1);
                    *(__nv_bfloat162*)&Ch[off] = __nv_bfloat162(h0, h1);
                    *(__nv_bfloat162*)&Cl[off] = __nv_bfloat162(l0, l1);
                }
            }
        }
}

// ======================= Flash attention via mma.sync (bf16x3) =======================
// q-tile 64 x 64, k-tile 64. 128 threads = 4 warps; warp wm owns q rows wm*16..+15.
// smem: Qh Ql Kh Kl [row][d], Vh Vl [key][d] (B via ldmatrix.trans). stride 72 bf16.
#define FST 72
#define FTS (64 * FST)            // bf16 elems per tile
#define FA_SMEM (6 * FTS * 2)     // 55296 bytes
__global__ void __launch_bounds__(128) flash_mma(
    const float* __restrict__ QKV,
    __nv_bfloat16* __restrict__ Oh, __nv_bfloat16* __restrict__ Ol)
{
    extern __shared__ __nv_bfloat16 fs[];
    uint32_t sb = smem_u32(fs);
    const uint32_t QH = 0, QL = FTS * 2, KH = 2 * FTS * 2, KL = 3 * FTS * 2,
                   VH = 4 * FTS * 2, VL = 5 * FTS * 2;

    int qt = blockIdx.x, hh = blockIdx.y, b = blockIdx.z;
    int tid = threadIdx.x, lane = tid & 31, wm = tid >> 5;
    const int LDX = 3 * N_EMBD;
    const float* Qf = QKV + (size_t)b * SEQ * LDX + hh * DHEAD;
    const float* Kf = Qf + N_EMBD;
    const float* Vf = Qf + 2 * N_EMBD;
    int q0 = qt * 64;

    // ---- load Q tile (convert + split): 64 rows x 16 float4 = 1024 items, 8 iters @128thr ----
    #pragma unroll
    for (int i = 0; i < 8; i++) {
        int f = tid + i * 128;
        int r = f >> 4, c4 = f & 15;
        float4 qv = *(const float4*)&Qf[(size_t)(q0 + r) * LDX + c4 * 4];
        uint32_t hi0, lo0, hi1, lo1;
        pack_split2(qv.x, qv.y, hi0, lo0);
        pack_split2(qv.z, qv.w, hi1, lo1);
        uint32_t o = (uint32_t)(r * FST + c4 * 4) * 2;
        *(uint32_t*)((char*)fs + QH + o)     = hi0;
        *(uint32_t*)((char*)fs + QH + o + 4) = hi1;
        *(uint32_t*)((char*)fs + QL + o)     = lo0;
        *(uint32_t*)((char*)fs + QL + o + 4) = lo1;
    }

    float Sf[8][4], Of[8][4];
    float mrow[2] = {-1e30f, -1e30f}, lrow[2] = {0.f, 0.f};
    #pragma unroll
    for (int j = 0; j < 8; j++)
        #pragma unroll
        for (int e = 0; e < 4; e++) Of[j][e] = 0.f;

    int lrw = lane & 15, lcl = lane >> 4;
    uint32_t qoff = ((uint32_t)(wm * 16 + lrw) * FST + lcl * 8) * 2;
    uint32_t koff = ((uint32_t)lrw * FST + lcl * 8) * 2;

    for (int kt = 0; kt <= qt; kt++) {
        int k0 = kt * 64;
        __syncthreads();
        // ---- load K, V tiles: 1024 items each, 8 iters @128thr ----
        #pragma unroll
        for (int i = 0; i < 8; i++) {
            int f = tid + i * 128;
            int r = f >> 4, c4 = f & 15;
            uint32_t o = (uint32_t)(r * FST + c4 * 4) * 2;
            float4 kv = *(const float4*)&Kf[(size_t)(k0 + r) * LDX + c4 * 4];
            uint32_t hi0, lo0, hi1, lo1;
            pack_split2(kv.x, kv.y, hi0, lo0);
            pack_split2(kv.z, kv.w, hi1, lo1);
            *(uint32_t*)((char*)fs + KH + o)     = hi0;
            *(uint32_t*)((char*)fs + KH + o + 4) = hi1;
            *(uint32_t*)((char*)fs + KL + o)     = lo0;
            *(uint32_t*)((char*)fs + KL + o + 4) = lo1;
            float4 vv = *(const float4*)&Vf[(size_t)(k0 + r) * LDX + c4 * 4];
            pack_split2(vv.x, vv.y, hi0, lo0);
            pack_split2(vv.z, vv.w, hi1, lo1);
            *(uint32_t*)((char*)fs + VH + o)     = hi0;
            *(uint32_t*)((char*)fs + VH + o + 4) = hi1;
            *(uint32_t*)((char*)fs + VL + o)     = lo0;
            *(uint32_t*)((char*)fs + VL + o + 4) = lo1;
        }
        __syncthreads();

        // ---- S = Q K^T (bf16x3) ----
        #pragma unroll
        for (int j = 0; j < 8; j++)
            #pragma unroll
            for (int e = 0; e < 4; e++) Sf[j][e] = 0.f;
        #pragma unroll
        for (int c = 0; c < 4; c++) {
            uint32_t a_h[4], a_l[4];
            ldsm4(a_h, sb + QH + qoff + c * 32);
            ldsm4(a_l, sb + QL + qoff + c * 32);
            #pragma unroll
            for (int g = 0; g < 4; g++) {
                uint32_t kh[4], kl[4];
                uint32_t o = koff + g * (16 * FST * 2) + c * 32;
                ldsm4(kh, sb + KH + o);
                ldsm4(kl, sb + KL + o);
                mma16816(Sf[2 * g],     a_h, kh[0], kh[2]);
                mma16816(Sf[2 * g + 1], a_h, kh[1], kh[3]);
                mma16816(Sf[2 * g],     a_h, kl[0], kl[2]);
                mma16816(Sf[2 * g + 1], a_h, kl[1], kl[3]);
                mma16816(Sf[2 * g],     a_l, kh[0], kh[2]);
                mma16816(Sf[2 * g + 1], a_l, kh[1], kh[3]);
            }
        }

        // ---- scale + causal mask ----
        bool diag = (kt == qt);
        #pragma unroll
        for (int j = 0; j < 8; j++)
            #pragma unroll
            for (int e = 0; e < 4; e++) {
                float s = Sf[j][e] * 0.03125f;
                if (diag) {
                    int kg = k0 + j * 8 + (lane & 3) * 2 + (e & 1);
                    int qg = q0 + wm * 16 + (lane >> 2) + (e >> 1) * 8;
                    if (kg > qg) s = -1e30f;
                }
                Sf[j][e] = s;
            }

        // ---- online softmax (rows r and r+8) ----
        #pragma unroll
        for (int half = 0; half < 2; half++) {
            float mx = -1e30f;
            #pragma unroll
            for (int j = 0; j < 8; j++) {
                mx = fmaxf(mx, Sf[j][half * 2]);
                mx = fmaxf(mx, Sf[j][half * 2 + 1]);
            }
            mx = fmaxf(mx, __shfl_xor_sync(0xffffffffu, mx, 1));
            mx = fmaxf(mx, __shfl_xor_sync(0xffffffffu, mx, 2));
            float mnew  = fmaxf(mrow[half], mx);
            float alpha = exp2f((mrow[half] - mnew) * LOG2E);
            float psum = 0.f;
            #pragma unroll
            for (int j = 0; j < 8; j++) {
                float p0 = exp2f((Sf[j][half * 2]     - mnew) * LOG2E);
                float p1 = exp2f((Sf[j][half * 2 + 1] - mnew) * LOG2E);
                Sf[j][half * 2]     = p0;
                Sf[j][half * 2 + 1] = p1;
                psum += p0 + p1;
            }
            psum += __shfl_xor_sync(0xffffffffu, psum, 1);
            psum += __shfl_xor_sync(0xffffffffu, psum, 2);
            lrow[half] = lrow[half] * alpha + psum;
            mrow[half] = mnew;
            #pragma unroll
            for (int j = 0; j < 8; j++) {
                Of[j][half * 2]     *= alpha;
                Of[j][half * 2 + 1] *= alpha;
            }
        }

        // ---- O += P V (bf16x3, P from S-frags) ----
        #pragma unroll
        for (int t = 0; t < 4; t++) {
            uint32_t pa_h[4], pa_l[4];
            pack_split2(Sf[2 * t][0],     Sf[2 * t][1],     pa_h[0], pa_l[0]);
            pack_split2(Sf[2 * t][2],     Sf[2 * t][3],     pa_h[1], pa_l[1]);
            pack_split2(Sf[2 * t + 1][0], Sf[2 * t + 1][1], pa_h[2], pa_l[2]);
            pack_split2(Sf[2 * t + 1][2], Sf[2 * t + 1][3], pa_h[3], pa_l[3]);
            #pragma unroll
            for (int g = 0; g < 4; g++) {
                uint32_t vh[4], vl[4];
                uint32_t o = ((uint32_t)(t * 16 + lrw) * FST + g * 16 + lcl * 8) * 2;
                ldsm4t(vh, sb + VH + o);
                ldsm4t(vl, sb + VL + o);
                mma16816(Of[2 * g],     pa_h, vh[0], vh[1]);
                mma16816(Of[2 * g + 1], pa_h, vh[2], vh[3]);
                mma16816(Of[2 * g],     pa_h, vl[0], vl[1]);
                mma16816(Of[2 * g + 1], pa_h, vl[2], vl[3]);
                mma16816(Of[2 * g],     pa_l, vh[0], vh[1]);
                mma16816(Of[2 * g + 1], pa_l, vh[2], vh[3]);
            }
        }
    }

    // ---- finalize: /l, split, store (batch offset included!) ----
    float inv0 = 1.0f / lrow[0], inv1 = 1.0f / lrow[1];
    #pragma unroll
    for (int j = 0; j < 8; j++) {
        #pragma unroll
        for (int half = 0; half < 2; half++) {
            float inv = half ? inv1 : inv0;
            float o0 = Of[j][half * 2] * inv, o1 = Of[j][half * 2 + 1] * inv;
            int row = q0 + wm * 16 + (lane >> 2) + half * 8;
            int col = hh * DHEAD + j * 8 + (lane & 3) * 2;
            uint32_t hi, lo;
            pack_split2(o0, o1, hi, lo);
            size_t off = ((size_t)b * SEQ + row) * N_EMBD + col;
            *(uint32_t*)&Oh[off] = hi;
            *(uint32_t*)&Ol[off] = lo;
        }
    }
}

// ======================= launch =======================
extern "C" void kernel_launch(void* const* d_in, const int* in_sizes, int n_in,
                              void* d_out, int out_size)
{
    (void)in_sizes; (void)n_in; (void)out_size;
    const float* x     = (const float*)d_in[0];
    const float* Wq    = (const float*)d_in[1];
    const float* Wk    = (const float*)d_in[2];
    const float* Wv    = (const float*)d_in[3];
    const float* Wproj = (const float*)d_in[4];
    const float* bproj = (const float*)d_in[5];
    const float* W1    = (const float*)d_in[6];
    const float* b1    = (const float*)d_in[7];
    const float* W2    = (const float*)d_in[8];
    const float* b2    = (const float*)d_in[9];
    const float* ln1w  = (const float*)d_in[10];
    const float* ln1b  = (const float*)d_in[11];
    const float* ln2w  = (const float*)d_in[12];
    const float* ln2b  = (const float*)d_in[13];
    float* out = (float*)d_out;

    __nv_bfloat16 *h_hi, *h_lo, *at_hi, *at_lo, *ff_hi, *ff_lo;
    __nv_bfloat16 *wqkv_hi, *wqkv_lo, *wp_hi, *wp_lo, *w1_hi, *w1_lo, *w2_hi, *w2_lo;
    float* qkv;
    cudaGetSymbolAddress((void**)&h_hi,  g_h_hi);   cudaGetSymbolAddress((void**)&h_lo,  g_h_lo);
    cudaGetSymbolAddress((void**)&at_hi, g_at_hi);  cudaGetSymbolAddress((void**)&at_lo, g_at_lo);
    cudaGetSymbolAddress((void**)&ff_hi, g_ff_hi);  cudaGetSymbolAddress((void**)&ff_lo, g_ff_lo);
    cudaGetSymbolAddress((void**)&wqkv_hi, g_wqkv_hi); cudaGetSymbolAddress((void**)&wqkv_lo, g_wqkv_lo);
    cudaGetSymbolAddress((void**)&wp_hi, g_wp_hi);  cudaGetSymbolAddress((void**)&wp_lo, g_wp_lo);
    cudaGetSymbolAddress((void**)&w1_hi, g_w1_hi);  cudaGetSymbolAddress((void**)&w1_lo, g_w1_lo);
    cudaGetSymbolAddress((void**)&w2_hi, g_w2_hi);  cudaGetSymbolAddress((void**)&w2_lo, g_w2_lo);
    cudaGetSymbolAddress((void**)&qkv, g_qkv);

    cudaFuncSetAttribute(flash_mma, cudaFuncAttributeMaxDynamicSharedMemorySize, FA_SMEM);
    cudaFuncSetAttribute(tgemm<0>, cudaFuncAttributeMaxDynamicSharedMemorySize, TG_SMEM);
    cudaFuncSetAttribute(tgemm<1>, cudaFuncAttributeMaxDynamicSharedMemorySize, TG_SMEM);
    cudaFuncSetAttribute(tgemm<2>, cudaFuncAttributeMaxDynamicSharedMemorySize, TG_SMEM);

    dim3 tsb(32, 8);
    const size_t WSL = (size_t)N_EMBD * N_EMBD;
    tsplit<<<dim3(N_EMBD / 32, N_EMBD / 32), tsb>>>(Wq, wqkv_hi, wqkv_lo, N_EMBD, N_EMBD);
    tsplit<<<dim3(N_EMBD / 32, N_EMBD / 32), tsb>>>(Wk, wqkv_hi + WSL, wqkv_lo + WSL, N_EMBD, N_EMBD);
    tsplit<<<dim3(N_EMBD / 32, N_EMBD / 32), tsb>>>(Wv, wqkv_hi + 2 * WSL, wqkv_lo + 2 * WSL, N_EMBD, N_EMBD);
    tsplit<<<dim3(N_EMBD / 32, N_EMBD / 32), tsb>>>(Wproj, wp_hi, wp_lo, N_EMBD, N_EMBD);
    tsplit<<<dim3(FFDIM / 32,  N_EMBD / 32), tsb>>>(W1, w1_hi, w1_lo, N_EMBD, FFDIM);
    tsplit<<<dim3(N_EMBD / 32, FFDIM / 32),  tsb>>>(W2, w2_hi, w2_lo, FFDIM, N_EMBD);

    dim3 gqkv(3 * N_EMBD / 128, MROWS / 128);   // (24, 32)
    dim3 g1(N_EMBD / 128, MROWS / 128);         // (8, 32)
    dim3 g2(FFDIM / 128,  MROWS / 128);         // (32, 32)
    dim3 ga(SEQ / 64, NHEAD, BATCH);            // (32, 16, 2)

    // h = LN1(x)
    ln_kernel<<<MROWS, 256>>>(x, ln1w, ln1b, h_hi, h_lo);
    // qkv = h @ [Wq|Wk|Wv]
    tgemm<0><<<gqkv, 256, TG_SMEM>>>(h_hi, h_lo, wqkv_hi, wqkv_lo, nullptr, nullptr,
                                     qkv, nullptr, nullptr, MROWS, 3 * N_EMBD, N_EMBD);
    // attn
    flash_mma<<<ga, 128, FA_SMEM>>>(qkv, at_hi, at_lo);
    // out = x + attn @ Wproj + bproj
    tgemm<1><<<g1, 256, TG_SMEM>>>(at_hi, at_lo, wp_hi, wp_lo, bproj, x,
                                   out, nullptr, nullptr, MROWS, N_EMBD, N_EMBD);
    // h = LN2(out)
    ln_kernel<<<MROWS, 256>>>(out, ln2w, ln2b, h_hi, h_lo);
    // ff = relu(h @ W1 + b1)
    tgemm<2><<<g2, 256, TG_SMEM>>>(h_hi, h_lo, w1_hi, w1_lo, b1, nullptr,
                                   nullptr, ff_hi, ff_lo, MROWS, FFDIM, N_EMBD);
    // out = out + ff @ W2 + b2
    tgemm<1><<<g1, 256, TG_SMEM>>>(ff_hi, ff_lo, w2_hi, w2_lo, b2, out,
                                   out, nullptr, nullptr, MROWS, N_EMBD, FFDIM);
}